// round 7
// baseline (speedup 1.0000x reference)
#include <cuda_runtime.h>
#include <math.h>

#define B_   2
#define S_   2048
#define DM_  1024
#define H_   16
#define HD_  64
#define MTOT (B_*S_)

// Scratch (alloc-free rule: __device__ globals)
__device__ float g_Q[MTOT*DM_];
__device__ float g_K[MTOT*DM_];
__device__ float g_V[MTOT*DM_];
__device__ float g_attn[MTOT*DM_];
__device__ float g_x[MTOT*DM_];

__device__ __forceinline__ unsigned f2tf(float f) {
    unsigned u; asm("cvt.rna.tf32.f32 %0, %1;" : "=r"(u) : "f"(f)); return u;
}

__device__ __forceinline__ void mma8(float* d, const unsigned* a, const unsigned* b, const float* c) {
    asm volatile("mma.sync.aligned.m16n8k8.row.col.f32.tf32.tf32.f32 "
        "{%0,%1,%2,%3}, {%4,%5,%6,%7}, {%8,%9}, {%10,%11,%12,%13};"
        : "=f"(d[0]), "=f"(d[1]), "=f"(d[2]), "=f"(d[3])
        : "r"(a[0]), "r"(a[1]), "r"(a[2]), "r"(a[3]),
          "r"(b[0]), "r"(b[1]),
          "f"(c[0]), "f"(c[1]), "f"(c[2]), "f"(c[3]));
}

__device__ __forceinline__ void cpa16(float* smem, const float* gmem) {
    unsigned sa = (unsigned)__cvta_generic_to_shared(smem);
    asm volatile("cp.async.ca.shared.global [%0], [%1], 16;" :: "r"(sa), "l"(gmem));
}
#define CP_COMMIT() asm volatile("cp.async.commit_group;")
#define CP_WAIT(N)  asm volatile("cp.async.wait_group %0;" :: "n"(N))

// ---------------------------------------------------------------------------
// tf32 tensor-core GEMM (NT), cp.async 2-stage pipeline.
// C[m][n] = sum_k A[m][k]*W[n][k] + bias[n] (+res). 128x128 tile, BK=16.
// 256 threads (8 warps 2x4), warp tile 64x32. smem stride 20 -> conflict-free.
// ---------------------------------------------------------------------------
template<bool ADD_RES>
__global__ __launch_bounds__(256)
void tgemm(const float* __restrict__ A, const float* __restrict__ W,
           const float* __restrict__ bias, const float* __restrict__ res, int which)
{
    __shared__ float As[2][128*20];
    __shared__ float Bs[2][128*20];

    const float* Abase = (A == nullptr) ? (const float*)g_attn : A;
    float* C = ADD_RES ? g_x : (which == 0 ? g_Q : (which == 1 ? g_K : g_V));

    const int tid = threadIdx.x;
    const int warp = tid >> 5, lane = tid & 31;
    const int g = lane >> 2, t = lane & 3;
    const int wm = warp >> 2, wn = warp & 3;
    const int m0 = blockIdx.y * 128, n0 = blockIdx.x * 128;

    const int lr  = tid >> 1;          // 0..127
    const int lcq = (tid & 1) * 8;     // 0 or 8
    const float* Ag = Abase + (size_t)(m0 + lr) * DM_ + lcq;
    const float* Wg = W     + (size_t)(n0 + lr) * DM_ + lcq;

    auto issue = [&](int st, int k0) {
        cpa16(&As[st][lr*20 + lcq],     Ag + k0);
        cpa16(&As[st][lr*20 + lcq + 4], Ag + k0 + 4);
        cpa16(&Bs[st][lr*20 + lcq],     Wg + k0);
        cpa16(&Bs[st][lr*20 + lcq + 4], Wg + k0 + 4);
        CP_COMMIT();
    };

    float acc[4][4][4];
    #pragma unroll
    for (int mt = 0; mt < 4; mt++)
        #pragma unroll
        for (int nt = 0; nt < 4; nt++)
            #pragma unroll
            for (int i = 0; i < 4; i++) acc[mt][nt][i] = 0.f;

    issue(0, 0);
    int st = 0;
    for (int k0 = 0; k0 < DM_; k0 += 16, st ^= 1) {
        CP_WAIT(0);
        __syncthreads();
        if (k0 + 16 < DM_) issue(st ^ 1, k0 + 16);

        #pragma unroll
        for (int ks = 0; ks < 2; ks++) {
            unsigned af[4][4], bf[4][2];
            #pragma unroll
            for (int mt = 0; mt < 4; mt++) {
                int base = (wm*64 + mt*16 + g)*20 + ks*8 + t;
                af[mt][0] = f2tf(As[st][base]);
                af[mt][1] = f2tf(As[st][base + 160]);
                af[mt][2] = f2tf(As[st][base + 4]);
                af[mt][3] = f2tf(As[st][base + 164]);
            }
            #pragma unroll
            for (int nt = 0; nt < 4; nt++) {
                int base = (wn*32 + nt*8 + g)*20 + ks*8 + t;
                bf[nt][0] = f2tf(Bs[st][base]);
                bf[nt][1] = f2tf(Bs[st][base + 4]);
            }
            #pragma unroll
            for (int mt = 0; mt < 4; mt++)
                #pragma unroll
                for (int nt = 0; nt < 4; nt++)
                    mma8(acc[mt][nt], af[mt], bf[nt], acc[mt][nt]);
        }
    }

    #pragma unroll
    for (int mt = 0; mt < 4; mt++) {
        int row = m0 + wm*64 + mt*16 + g;
        #pragma unroll
        for (int nt = 0; nt < 4; nt++) {
            int col = n0 + wn*32 + nt*8 + 2*t;
            float2 bv = *(const float2*)&bias[col];
            float v0 = acc[mt][nt][0] + bv.x, v1 = acc[mt][nt][1] + bv.y;
            float v2 = acc[mt][nt][2] + bv.x, v3 = acc[mt][nt][3] + bv.y;
            if (ADD_RES) {
                float2 r0 = *(const float2*)&res[(size_t)row*DM_ + col];
                float2 r1 = *(const float2*)&res[(size_t)(row+8)*DM_ + col];
                v0 += r0.x; v1 += r0.y; v2 += r1.x; v3 += r1.y;
            }
            *(float2*)&C[(size_t)row*DM_ + col]     = make_float2(v0, v1);
            *(float2*)&C[(size_t)(row+8)*DM_ + col] = make_float2(v2, v3);
        }
    }
}

// ---------------------------------------------------------------------------
// Flash attention, tf32 mma, cp.async double-buffered K/V tiles.
// Block = 128 threads (4 warps), 64 query rows. KV tiles of 64.
// Dynamic smem: K[2][64*68] | V[2][64*68] | P[64*68]  = 87040 B.
// One __syncthreads per tile; P round-trip is warp-private (syncwarp only).
// Raw fp32 bits fed to mma.tf32 (HW truncation) except Q (rna + pre-scale).
// ---------------------------------------------------------------------------
#define TSTRIDE 68
#define TSZ     (64*TSTRIDE)

__global__ __launch_bounds__(128)
void flash_tc(const int* __restrict__ mask)
{
    extern __shared__ float sm[];
    float* Ps = sm + 4*TSZ;

    const int tid = threadIdx.x;
    const int warp = tid >> 5, lane = tid & 31;
    const int g = lane >> 2, t = lane & 3;
    const int q0 = blockIdx.x * 64;
    const int bh = blockIdx.y, b = bh >> 4, h = bh & 15;
    const int wq = warp * 16;

    const int cr = tid >> 4;           // copy row base 0..7
    const int cc = (tid & 15) * 4;     // copy col 0..60

    const float* qsrc  = g_Q + ((size_t)(b*S_ + q0))*DM_ + h*HD_;
    const float* ksrc0 = g_K + ((size_t)b*S_)*DM_ + h*HD_;
    const float* vsrc0 = g_V + ((size_t)b*S_)*DM_ + h*HD_;

    auto issueKV = [&](int buf, int k0) {
        float* Kd = sm + buf*TSZ;
        float* Vd = sm + 2*TSZ + buf*TSZ;
        const float* kp = ksrc0 + (size_t)k0*DM_;
        const float* vp = vsrc0 + (size_t)k0*DM_;
        #pragma unroll
        for (int j = 0; j < 8; j++) {
            int rr = cr + j*8;
            cpa16(&Kd[rr*TSTRIDE + cc], kp + (size_t)rr*DM_ + cc);
            cpa16(&Vd[rr*TSTRIDE + cc], vp + (size_t)rr*DM_ + cc);
        }
        CP_COMMIT();
    };

    // Stage Q into Ps, and tile 0 of K/V into buffer 0.
    #pragma unroll
    for (int j = 0; j < 8; j++) {
        int rr = cr + j*8;
        cpa16(&Ps[rr*TSTRIDE + cc], qsrc + (size_t)rr*DM_ + cc);
    }
    CP_COMMIT();
    issueKV(0, 0);

    CP_WAIT(1);              // Q group complete
    __syncthreads();

    unsigned qf[8][4];
    #pragma unroll
    for (int ks = 0; ks < 8; ks++) {
        int base = (wq + g)*TSTRIDE + ks*8 + t;
        qf[ks][0] = f2tf(Ps[base]            * 0.125f);
        qf[ks][1] = f2tf(Ps[base + 8*TSTRIDE]* 0.125f);
        qf[ks][2] = f2tf(Ps[base + 4]        * 0.125f);
        qf[ks][3] = f2tf(Ps[base + 8*TSTRIDE + 4] * 0.125f);
    }

    float o[8][4];
    #pragma unroll
    for (int nt = 0; nt < 8; nt++)
        #pragma unroll
        for (int i = 0; i < 4; i++) o[nt][i] = 0.f;
    float mi[2] = {-1e30f, -1e30f}, li[2] = {0.f, 0.f};

    const int* mrow0 = mask + ((size_t)b*S_ + q0 + wq + g)*S_;
    const int* mrow1 = mrow0 + 8*S_;

    int cur = 0;
    for (int i = 0; i < 32; i++, cur ^= 1) {
        CP_WAIT(0);
        __syncthreads();
        if (i + 1 < 32) issueKV(cur ^ 1, (i + 1)*64);

        const float* K = sm + cur*TSZ;
        const float* V = sm + 2*TSZ + cur*TSZ;

        // S = Q K^T
        float s[8][4];
        #pragma unroll
        for (int nt = 0; nt < 8; nt++)
            #pragma unroll
            for (int i2 = 0; i2 < 4; i2++) s[nt][i2] = 0.f;

        #pragma unroll
        for (int ks = 0; ks < 8; ks++) {
            #pragma unroll
            for (int nt = 0; nt < 8; nt++) {
                unsigned bf[2];
                int base = (nt*8 + g)*TSTRIDE + ks*8 + t;
                bf[0] = __float_as_uint(K[base]);
                bf[1] = __float_as_uint(K[base + 4]);
                mma8(s[nt], qf[ks], bf, s[nt]);
            }
        }

        // Mask
        const int k0 = i*64;
        #pragma unroll
        for (int nt = 0; nt < 8; nt++) {
            int c = k0 + nt*8 + 2*t;
            int2 m0v = *(const int2*)&mrow0[c];
            int2 m1v = *(const int2*)&mrow1[c];
            if (m0v.x == 0) s[nt][0] = -1e9f;
            if (m0v.y == 0) s[nt][1] = -1e9f;
            if (m1v.x == 0) s[nt][2] = -1e9f;
            if (m1v.y == 0) s[nt][3] = -1e9f;
        }

        // Online softmax
        #pragma unroll
        for (int rr = 0; rr < 2; rr++) {
            float mx = -1e30f;
            #pragma unroll
            for (int nt = 0; nt < 8; nt++)
                mx = fmaxf(mx, fmaxf(s[nt][2*rr], s[nt][2*rr+1]));
            mx = fmaxf(mx, __shfl_xor_sync(0xffffffffu, mx, 1));
            mx = fmaxf(mx, __shfl_xor_sync(0xffffffffu, mx, 2));
            float mnew = fmaxf(mi[rr], mx);
            float alpha = __expf(mi[rr] - mnew);
            float sum = 0.f;
            #pragma unroll
            for (int nt = 0; nt < 8; nt++) {
                s[nt][2*rr]   = __expf(s[nt][2*rr]   - mnew);
                s[nt][2*rr+1] = __expf(s[nt][2*rr+1] - mnew);
                sum += s[nt][2*rr] + s[nt][2*rr+1];
            }
            sum += __shfl_xor_sync(0xffffffffu, sum, 1);
            sum += __shfl_xor_sync(0xffffffffu, sum, 2);
            li[rr] = li[rr]*alpha + sum;
            mi[rr] = mnew;
            #pragma unroll
            for (int nt = 0; nt < 8; nt++) {
                o[nt][2*rr]   *= alpha;
                o[nt][2*rr+1] *= alpha;
            }
        }

        // P -> smem (warp-private rows; raw fp32 bits)
        #pragma unroll
        for (int nt = 0; nt < 8; nt++) {
            int base = (wq + g)*TSTRIDE + nt*8 + 2*t;
            *(float2*)&Ps[base]             = make_float2(s[nt][0], s[nt][1]);
            *(float2*)&Ps[base + 8*TSTRIDE] = make_float2(s[nt][2], s[nt][3]);
        }
        __syncwarp();

        // O += P V
        #pragma unroll
        for (int ks = 0; ks < 8; ks++) {
            unsigned pa[4];
            int base = (wq + g)*TSTRIDE + ks*8 + t;
            pa[0] = __float_as_uint(Ps[base]);
            pa[1] = __float_as_uint(Ps[base + 8*TSTRIDE]);
            pa[2] = __float_as_uint(Ps[base + 4]);
            pa[3] = __float_as_uint(Ps[base + 8*TSTRIDE + 4]);
            #pragma unroll
            for (int nt = 0; nt < 8; nt++) {
                unsigned bf[2];
                bf[0] = __float_as_uint(V[(ks*8 + t)*TSTRIDE + nt*8 + g]);
                bf[1] = __float_as_uint(V[(ks*8 + t + 4)*TSTRIDE + nt*8 + g]);
                mma8(o[nt], pa, bf, o[nt]);
            }
        }
        __syncwarp();   // P reads done before next tile's P writes
    }

    // Epilogue
    float inv0 = 1.f / li[0], inv1 = 1.f / li[1];
    float* dst0 = g_attn + ((size_t)(b*S_ + q0 + wq + g))*DM_ + h*HD_;
    float* dst1 = dst0 + (size_t)8*DM_;
    #pragma unroll
    for (int nt = 0; nt < 8; nt++) {
        int c = nt*8 + 2*t;
        *(float2*)&dst0[c] = make_float2(o[nt][0]*inv0, o[nt][1]*inv0);
        *(float2*)&dst1[c] = make_float2(o[nt][2]*inv1, o[nt][3]*inv1);
    }
}

// ---------------------------------------------------------------------------
// LayerNorm: unbiased std (ddof=1), denominator (std + eps). One block per row.
// ---------------------------------------------------------------------------
__global__ __launch_bounds__(256)
void layernorm(const float* __restrict__ gamma, const float* __restrict__ beta,
               float* __restrict__ out)
{
    __shared__ float red[2][8];
    const int row = blockIdx.x;
    const int tid = threadIdx.x;
    const float* xr = g_x + (size_t)row * DM_;
    const int c = tid * 4;

    float4 xv = *(const float4*)(xr + c);
    float sum = xv.x + xv.y + xv.z + xv.w;
    float sq  = xv.x*xv.x + xv.y*xv.y + xv.z*xv.z + xv.w*xv.w;

    #pragma unroll
    for (int off = 16; off > 0; off >>= 1) {
        sum += __shfl_xor_sync(0xffffffffu, sum, off);
        sq  += __shfl_xor_sync(0xffffffffu, sq,  off);
    }
    const int w = tid >> 5, lane = tid & 31;
    if (lane == 0) { red[0][w] = sum; red[1][w] = sq; }
    __syncthreads();
    if (tid == 0) {
        float s = 0.f, q = 0.f;
        #pragma unroll
        for (int i = 0; i < 8; i++) { s += red[0][i]; q += red[1][i]; }
        red[0][0] = s; red[1][0] = q;
    }
    __syncthreads();
    sum = red[0][0]; sq = red[1][0];

    float mean = sum / (float)DM_;
    float var  = (sq - (float)DM_ * mean * mean) / (float)(DM_ - 1);
    var = fmaxf(var, 0.f);
    float inv = 1.f / (sqrtf(var) + 1e-6f);

    float4 g4 = *(const float4*)(gamma + c);
    float4 b4 = *(const float4*)(beta + c);
    float4 ov;
    ov.x = g4.x * (xv.x - mean) * inv + b4.x;
    ov.y = g4.y * (xv.y - mean) * inv + b4.y;
    ov.z = g4.z * (xv.z - mean) * inv + b4.z;
    ov.w = g4.w * (xv.w - mean) * inv + b4.w;
    *(float4*)(out + (size_t)row * DM_ + c) = ov;
}

// ---------------------------------------------------------------------------
extern "C" void kernel_launch(void* const* d_in, const int* in_sizes, int n_in,
                              void* d_out, int out_size)
{
    (void)in_sizes; (void)n_in; (void)out_size;
    const float* query = (const float*)d_in[0];
    const float* key_  = (const float*)d_in[1];
    const float* value = (const float*)d_in[2];
    const int*   mask  = (const int*)  d_in[3];
    const float* Wq = (const float*)d_in[4];
    const float* bq = (const float*)d_in[5];
    const float* Wk = (const float*)d_in[6];
    const float* bk = (const float*)d_in[7];
    const float* Wv = (const float*)d_in[8];
    const float* bv = (const float*)d_in[9];
    const float* Wo = (const float*)d_in[10];
    const float* bo = (const float*)d_in[11];
    const float* gamma = (const float*)d_in[12];
    const float* beta  = (const float*)d_in[13];
    float* out = (float*)d_out;

    const int flash_smem = 5 * TSZ * (int)sizeof(float);  // 87040 B
    cudaFuncSetAttribute(flash_tc, cudaFuncAttributeMaxDynamicSharedMemorySize, flash_smem);

    dim3 gg(DM_/128, MTOT/128);   // (8, 32)
    tgemm<false><<<gg, 256>>>(query, Wq, bq, nullptr, 0);
    tgemm<false><<<gg, 256>>>(key_,  Wk, bk, nullptr, 1);
    tgemm<false><<<gg, 256>>>(value, Wv, bv, nullptr, 2);

    flash_tc<<<dim3(S_/64, B_*H_), 128, flash_smem>>>(mask);

    tgemm<true><<<gg, 256>>>(nullptr, Wo, bo, query, 3);

    layernorm<<<MTOT, 256>>>(gamma, beta, out);
}